// round 10
// baseline (speedup 1.0000x reference)
#include <cuda_runtime.h>
#include <cuda_bf16.h>
#include <cuda_fp8.h>
#include <math.h>
#include <stdint.h>

// Problem constants
#define Bb   8
#define SEQ  1024
#define Dd   768
#define Hh   12
#define Zz   64
#define Mm   3072
#define ROWS (Bb * SEQ)           // 8192
#define QKN  (2 * Dd)             // 1536 (Q cols then K cols)
#define NTIL (Mm / 128)           // 24 hopfield n-tiles
#define ATTN_BETA 0.125f
#define LOG2E 1.4426950408889634f
#define LN2   0.6931471805599453f
#define WSCALE 16.0f              // weight pre-scale (power of 2, exact)
#define WUNSCALE 0.0625f
#define QSCALE (WUNSCALE * ATTN_BETA * LOG2E)

// scratch (device globals: allocation-guard safe)
__device__ uint8_t g_g8  [(size_t)ROWS * Dd];
__device__ uint8_t g_wqk8[QKN * Dd];
__device__ uint8_t g_whn8[Mm * Dd];
__device__ uint8_t g_QK8 [(size_t)ROWS * QKN];     // 12.6 MB e4m3 Q|K
__device__ float   g_hn_part[(size_t)ROWS * NTIL];
__device__ double  g_attn_sum;
__device__ double  g_hn_sum;

// ---------------------------------------------------------------------------
// One merged conversion kernel: zeros sums, converts g/wq/wk/w_hn to e4m3.
// ---------------------------------------------------------------------------
#define NG_BLK  (ROWS * Dd / 2048)          // 3072
#define NW_BLK  (Hh * Zz * Dd / 2048)       // 288
#define NH_BLK  (Mm * Dd / 2048)            // 1152
#define CVT_BLOCKS (NG_BLK + 2 * NW_BLK + NH_BLK)

__global__ void cvt_all_kernel(const float* __restrict__ g,
                               const float* __restrict__ wq,
                               const float* __restrict__ wk,
                               const float* __restrict__ whn) {
    if (blockIdx.x == 0 && threadIdx.x == 0) { g_attn_sum = 0.0; g_hn_sum = 0.0; }
    int b = blockIdx.x;
    const float* src; uint8_t* dst; float scale;
    if (b < NG_BLK)                       { src = g;   dst = g_g8;              scale = 1.0f;  }
    else if ((b -= NG_BLK) < NW_BLK)      { src = wq;  dst = g_wqk8;            scale = WSCALE; }
    else if ((b -= NW_BLK) < NW_BLK)      { src = wk;  dst = g_wqk8 + Hh*Zz*Dd; scale = WSCALE; }
    else { b -= NW_BLK;                     src = whn; dst = g_whn8;            scale = WSCALE; }

    int i = (b * 256 + threadIdx.x) * 8;
    float4 a = *(const float4*)(src + i);
    float4 c = *(const float4*)(src + i + 4);
    __nv_fp8x2_storage_t p0 = __nv_cvt_float2_to_fp8x2(
        make_float2(a.x * scale, a.y * scale), __NV_SATFINITE, __NV_E4M3);
    __nv_fp8x2_storage_t p1 = __nv_cvt_float2_to_fp8x2(
        make_float2(a.z * scale, a.w * scale), __NV_SATFINITE, __NV_E4M3);
    __nv_fp8x2_storage_t p2 = __nv_cvt_float2_to_fp8x2(
        make_float2(c.x * scale, c.y * scale), __NV_SATFINITE, __NV_E4M3);
    __nv_fp8x2_storage_t p3 = __nv_cvt_float2_to_fp8x2(
        make_float2(c.z * scale, c.w * scale), __NV_SATFINITE, __NV_E4M3);
    uint2 o;
    o.x = (uint32_t)p0 | ((uint32_t)p1 << 16);
    o.y = (uint32_t)p2 | ((uint32_t)p3 << 16);
    *(uint2*)(dst + i) = o;
}

// ---------------------------------------------------------------------------
// PTX helpers
// ---------------------------------------------------------------------------
__device__ __forceinline__ uint32_t smem_u32(const void* p) {
    return (uint32_t)__cvta_generic_to_shared(p);
}
__device__ __forceinline__ void ldsm_x4(uint32_t& r0, uint32_t& r1,
                                        uint32_t& r2, uint32_t& r3, uint32_t addr) {
    asm volatile("ldmatrix.sync.aligned.m8n8.x4.shared.b16 {%0,%1,%2,%3}, [%4];"
                 : "=r"(r0), "=r"(r1), "=r"(r2), "=r"(r3) : "r"(addr));
}
__device__ __forceinline__ void mma_fp8(float* d, const uint32_t* a, const uint32_t* b) {
    asm volatile(
        "mma.sync.aligned.m16n8k32.row.col.f32.e4m3.e4m3.f32 "
        "{%0,%1,%2,%3}, {%4,%5,%6,%7}, {%8,%9}, {%0,%1,%2,%3};"
        : "+f"(d[0]), "+f"(d[1]), "+f"(d[2]), "+f"(d[3])
        : "r"(a[0]), "r"(a[1]), "r"(a[2]), "r"(a[3]), "r"(b[0]), "r"(b[1]));
}
__device__ __forceinline__ void cp16(uint32_t smem, const void* g) {
    asm volatile("cp.async.cg.shared.global [%0], [%1], 16;" :: "r"(smem), "l"(g));
}
__device__ __forceinline__ void cp_commit() {
    asm volatile("cp.async.commit_group;" ::: "memory");
}
template <int N>
__device__ __forceinline__ void cp_wait() {
    asm volatile("cp.async.wait_group %0;" :: "n"(N) : "memory");
}
__device__ __forceinline__ float fex2(float x) {
    float r;
    asm("ex2.approx.ftz.f32 %0, %1;" : "=f"(r) : "f"(x));
    return r;
}
__device__ __forceinline__ float exp2_sum16(const float* v) {
    float e[16];
#pragma unroll
    for (int u = 0; u < 16; ++u) e[u] = fex2(v[u]);
#pragma unroll
    for (int st = 8; st > 0; st >>= 1)
#pragma unroll
        for (int u = 0; u < st; ++u) e[u] += e[u + st];
    return e[0];
}
__device__ __forceinline__ uint16_t fp8x2(float a, float b) {
    return (uint16_t)__nv_cvt_float2_to_fp8x2(make_float2(a, b),
                                              __NV_SATFINITE, __NV_E4M3);
}

#define GSTR  80                 // bytes per smem row (64 + 16 pad)
#define STG_B (128 * GSTR)       // 10240 bytes per operand per stage
#define NCH8  (Dd / 64)          // 12 chunks
#define SMEM_DYN (3 * 2 * STG_B) // 61440 B

// ---------------------------------------------------------------------------
// FP8 GEMM body. FUSE=false: store e4m3 C (Q tile absorbs beta*log2e*2,
// K tile absorbs 0.5 -> product is log2-domain score directly).
// FUSE=true: fused Hopfield exp2-sum partials.
// ---------------------------------------------------------------------------
template <bool FUSE>
__device__ __forceinline__
void gemm_body(char* dynsm, float (*red)[128], int bx, int by,
               const uint8_t* __restrict__ A, const uint8_t* __restrict__ B,
               uint8_t* __restrict__ C, int N,
               const float* __restrict__ beta_ptr) {
    const int tid  = threadIdx.x;
    const int warp = tid >> 5, lane = tid & 31;
    const int wm = warp >> 1, wn = warp & 1;
    const int m0 = by * 128, n0 = bx * 128;

    const int lrow0 = tid >> 2, lc4 = tid & 3;
    const uint8_t* Ag0 = A + (size_t)(m0 + lrow0) * Dd + lc4 * 16;
    const uint8_t* Ag1 = A + (size_t)(m0 + lrow0 + 64) * Dd + lc4 * 16;
    const uint8_t* Bg0 = B + (size_t)(n0 + lrow0) * Dd + lc4 * 16;
    const uint8_t* Bg1 = B + (size_t)(n0 + lrow0 + 64) * Dd + lc4 * 16;
    const uint32_t so0 = (uint32_t)(lrow0 * GSTR + lc4 * 16);
    const uint32_t so1 = so0 + (uint32_t)(64 * GSTR);
    const uint32_t smbase = smem_u32(dynsm);

    float acc[2][8][4];
#pragma unroll
    for (int i = 0; i < 2; ++i)
#pragma unroll
        for (int j = 0; j < 8; ++j)
#pragma unroll
            for (int k = 0; k < 4; ++k) acc[i][j][k] = 0.0f;

    const int arow   = wm * 32 + (lane & 15);
    const int acolB  = (lane >> 4) * 16;
    const int brow   = wn * 64 + (lane >> 4) * 8 + (lane & 7);
    const int bcolB  = ((lane >> 3) & 1) * 16;

    auto issue_chunk = [&](int j, int s) {
        const uint32_t ab = smbase + (uint32_t)(s * 2 * STG_B);
        const uint32_t bb = ab + STG_B;
        const int k0 = j * 64;
        cp16(ab + so0, Ag0 + k0);
        cp16(ab + so1, Ag1 + k0);
        cp16(bb + so0, Bg0 + k0);
        cp16(bb + so1, Bg1 + k0);
    };

    issue_chunk(0, 0); cp_commit();
    issue_chunk(1, 1); cp_commit();

    int stage = 0;
    for (int j = 0; j < NCH8; ++j) {
        cp_wait<1>();
        __syncthreads();
        if (j + 2 < NCH8) issue_chunk(j + 2, (stage + 2) % 3);
        cp_commit();

        const uint32_t ab = smbase + (uint32_t)(stage * 2 * STG_B);
        const uint32_t bb = ab + STG_B;
#pragma unroll
        for (int kk = 0; kk < 64; kk += 32) {
            uint32_t af[2][4];
#pragma unroll
            for (int mt = 0; mt < 2; ++mt)
                ldsm_x4(af[mt][0], af[mt][1], af[mt][2], af[mt][3],
                        ab + (uint32_t)((arow + mt * 16) * GSTR + acolB + kk));
            uint32_t bfr[4][4];
#pragma unroll
            for (int jj = 0; jj < 4; ++jj)
                ldsm_x4(bfr[jj][0], bfr[jj][1], bfr[jj][2], bfr[jj][3],
                        bb + (uint32_t)((brow + jj * 16) * GSTR + bcolB + kk));
#pragma unroll
            for (int mt = 0; mt < 2; ++mt)
#pragma unroll
                for (int jj = 0; jj < 4; ++jj) {
                    mma_fp8(acc[mt][2 * jj],     af[mt], &bfr[jj][0]);
                    mma_fp8(acc[mt][2 * jj + 1], af[mt], &bfr[jj][2]);
                }
        }
        stage = (stage + 1) % 3;
    }

    if (!FUSE) {
        // Q tiles (n0 < Dd): sc = QSCALE*2 ; K tiles: sc = WUNSCALE*0.5
        const float sc = (n0 < Dd) ? (QSCALE * 2.0f) : (WUNSCALE * 0.5f);
#pragma unroll
        for (int mt = 0; mt < 2; ++mt) {
            const int r = m0 + wm * 32 + mt * 16 + (lane >> 2);
#pragma unroll
            for (int nt = 0; nt < 8; ++nt) {
                const int c = n0 + wn * 64 + nt * 8 + (lane & 3) * 2;
                *(uint16_t*)(C + (size_t)r * N + c) =
                    fp8x2(acc[mt][nt][0] * sc, acc[mt][nt][1] * sc);
                *(uint16_t*)(C + (size_t)(r + 8) * N + c) =
                    fp8x2(acc[mt][nt][2] * sc, acc[mt][nt][3] * sc);
            }
        }
    } else {
        const float SC = beta_ptr[0] * LOG2E * WUNSCALE;
        float Sl[2][2];
#pragma unroll
        for (int mt = 0; mt < 2; ++mt) {
#pragma unroll
            for (int half = 0; half < 2; ++half) {
                float v[16];
#pragma unroll
                for (int nt = 0; nt < 8; ++nt) {
                    v[2 * nt]     = acc[mt][nt][2 * half]     * SC;
                    v[2 * nt + 1] = acc[mt][nt][2 * half + 1] * SC;
                }
                float S = exp2_sum16(v);
                S += __shfl_xor_sync(0xffffffffu, S, 1);
                S += __shfl_xor_sync(0xffffffffu, S, 2);
                Sl[mt][half] = S;
            }
        }
        if ((lane & 3) == 0) {
#pragma unroll
            for (int mt = 0; mt < 2; ++mt)
#pragma unroll
                for (int half = 0; half < 2; ++half)
                    red[wn][wm * 32 + mt * 16 + half * 8 + (lane >> 2)] = Sl[mt][half];
        }
        __syncthreads();
        const int tid2 = threadIdx.x;
        if (tid2 < 128) {
            g_hn_part[(size_t)(m0 + tid2) * NTIL + bx] = red[0][tid2] + red[1][tid2];
        }
    }
}

// ---------------------------------------------------------------------------
// Attention body: fp8 Q,K (log2-domain product), exp2-sum, no max.
// q-tile 128, K streamed in 64-row tiles. Warp = 16 q-rows.
// ---------------------------------------------------------------------------
__device__ __forceinline__
void attn_body(char* dynsm, float* red, int att_idx) {
    const int qt = att_idx & 7;
    const int h  = (att_idx >> 3) % Hh;
    const int b  = att_idx / (8 * Hh);
    const int q0 = qt * 128;

    uint8_t* Qs  = (uint8_t*)dynsm;            // 128*80 = 10240
    uint8_t* Ks0 = (uint8_t*)dynsm + 10240;    // 64*80 = 5120
    uint8_t* Ks1 = (uint8_t*)dynsm + 15360;

    const int tid  = threadIdx.x;
    const int wm   = tid >> 5, lane = tid & 31;

    const uint8_t* Kbase = g_QK8 + (size_t)(b * SEQ) * QKN + Dd + h * Zz;
    uint8_t* KsArr[2] = { Ks0, Ks1 };

    const int lrow = tid >> 2, lc4 = tid & 3;   // K: 1 cp16/thread; Q: 2

    auto issue_k = [&](int kt, int s) {
        cp16(smem_u32(KsArr[s] + lrow * GSTR + lc4 * 16),
             Kbase + (size_t)(kt * 64 + lrow) * QKN + lc4 * 16);
    };

    {
#pragma unroll
        for (int t = 0; t < 2; ++t) {
            int row = lrow + t * 64;
            cp16(smem_u32(Qs + row * GSTR + lc4 * 16),
                 g_QK8 + (size_t)(b * SEQ + q0 + row) * QKN + h * Zz + lc4 * 16);
        }
        cp_commit();
    }
    issue_k(0, 0); cp_commit();

    cp_wait<1>();
    __syncthreads();

    // Q fragments: m16 x k64 (two k32 steps), fp8 mapping identical to GEMM A
    const uint32_t qs_b = smem_u32(Qs);
    const int arow  = wm * 16 + (lane & 15);
    const int acolB = (lane >> 4) * 16;
    uint32_t qf[2][4];
#pragma unroll
    for (int zs = 0; zs < 2; ++zs)
        ldsm_x4(qf[zs][0], qf[zs][1], qf[zs][2], qf[zs][3],
                qs_b + (uint32_t)(arow * GSTR + acolB + zs * 32));

    const int brow  = (lane >> 4) * 8 + (lane & 7);
    const int bcolB = ((lane >> 3) & 1) * 16;

    float Ssum[2] = {0.0f, 0.0f};

    for (int kt = 0; kt < 16; ++kt) {
        cp_wait<0>();
        __syncthreads();
        if (kt + 1 < 16) issue_k(kt + 1, (kt + 1) & 1);
        cp_commit();

        const uint32_t ks_b = smem_u32(KsArr[kt & 1]);

        float acc[8][4];
#pragma unroll
        for (int j = 0; j < 8; ++j)
#pragma unroll
            for (int k = 0; k < 4; ++k) acc[j][k] = 0.0f;

#pragma unroll
        for (int zs = 0; zs < 2; ++zs) {
            uint32_t bfr[4][4];
#pragma unroll
            for (int j = 0; j < 4; ++j)
                ldsm_x4(bfr[j][0], bfr[j][1], bfr[j][2], bfr[j][3],
                        ks_b + (uint32_t)((brow + j * 16) * GSTR + bcolB + zs * 32));
#pragma unroll
            for (int j = 0; j < 4; ++j) {
                mma_fp8(acc[2 * j],     qf[zs], &bfr[j][0]);
                mma_fp8(acc[2 * j + 1], qf[zs], &bfr[j][2]);
            }
        }

        // accs ARE log2-domain scores: exp2 + tree sum
#pragma unroll
        for (int half = 0; half < 2; ++half) {
            float v[16];
#pragma unroll
            for (int j = 0; j < 8; ++j) {
                v[2 * j]     = acc[j][2 * half];
                v[2 * j + 1] = acc[j][2 * half + 1];
            }
            Ssum[half] += exp2_sum16(v);
        }
    }

#pragma unroll
    for (int half = 0; half < 2; ++half) {
        float s = Ssum[half];
        s += __shfl_xor_sync(0xffffffffu, s, 1);
        s += __shfl_xor_sync(0xffffffffu, s, 2);
        if ((lane & 3) == 0)
            red[wm * 16 + (lane >> 2) + half * 8] = s;
    }
    __syncthreads();

    if (tid < 128) {
        float lse = logf(red[tid]);
#pragma unroll
        for (int o = 16; o > 0; o >>= 1)
            lse += __shfl_xor_sync(0xffffffffu, lse, o);
        if ((tid & 31) == 0) atomicAdd(&g_attn_sum, (double)lse);
    }
}

// ---------------------------------------------------------------------------
// Kernel 1: QK projection GEMM only.  grid = (QKN/128, ROWS/128)
// ---------------------------------------------------------------------------
__global__ __launch_bounds__(256, 2)
void qk_gemm_kernel(const uint8_t* __restrict__ A, const uint8_t* __restrict__ B,
                    uint8_t* __restrict__ C, const float* __restrict__ beta_ptr) {
    extern __shared__ char dynsm[];
    gemm_body<false>(dynsm, nullptr, blockIdx.x, blockIdx.y, A, B, C, QKN, beta_ptr);
}

// ---------------------------------------------------------------------------
// Kernel 2: FUSED Hopfield GEMM + attention, interleaved 2:1.
// ---------------------------------------------------------------------------
#define HN_BLOCKS  (NTIL * (ROWS / 128))   // 1536
#define ATT_BLOCKS (8 * Hh * Bb)           // 768
#define FUSED_BLOCKS (HN_BLOCKS + ATT_BLOCKS)

__global__ __launch_bounds__(256, 2)
void hn_attn_kernel(const uint8_t* __restrict__ A, const uint8_t* __restrict__ B,
                    const float* __restrict__ beta_ptr) {
    extern __shared__ char dynsm[];
    __shared__ float red[2][128];
    const int bid = blockIdx.x;
    const int grp = bid / 3, r = bid - grp * 3;
    if (r < 2) {
        const int hn_idx = grp * 2 + r;
        gemm_body<true>(dynsm, red, hn_idx % NTIL, hn_idx / NTIL,
                        A, B, nullptr, Mm, beta_ptr);
    } else {
        attn_body(dynsm, &red[0][0], grp);
    }
}

// ---------------------------------------------------------------------------
// Combine Hopfield partials (float4 loads) + finalize
// ---------------------------------------------------------------------------
__global__ void hn_combine_kernel() {
    const int row = blockIdx.x * 256 + threadIdx.x;
    const float4* part = (const float4*)(g_hn_part + (size_t)row * NTIL);
    float4 p0 = part[0], p1 = part[1], p2 = part[2];
    float4 p3 = part[3], p4 = part[4], p5 = part[5];
    float S = ((p0.x + p0.y) + (p0.z + p0.w)) + ((p1.x + p1.y) + (p1.z + p1.w))
            + ((p2.x + p2.y) + (p2.z + p2.w)) + ((p3.x + p3.y) + (p3.z + p3.w))
            + ((p4.x + p4.y) + (p4.z + p4.w)) + ((p5.x + p5.y) + (p5.z + p5.w));
    float lse = logf(S);

    __shared__ float smr[256];
    smr[threadIdx.x] = lse;
    __syncthreads();
    for (int st = 128; st > 0; st >>= 1) {
        if (threadIdx.x < st) smr[threadIdx.x] += smr[threadIdx.x + st];
        __syncthreads();
    }
    if (threadIdx.x == 0) atomicAdd(&g_hn_sum, (double)smr[0]);
}

__global__ void finalize_kernel(const float* __restrict__ beta_ptr, float* out) {
    double beta = (double)beta_ptr[0];
    out[0] = (float)(-8.0 * g_attn_sum - (1.0 / beta) * g_hn_sum);
}

// ---------------------------------------------------------------------------
extern "C" void kernel_launch(void* const* d_in, const int* in_sizes, int n_in,
                              void* d_out, int out_size) {
    (void)in_sizes; (void)n_in; (void)out_size;
    const float* g    = (const float*)d_in[0];
    const float* wq   = (const float*)d_in[1];
    const float* wk   = (const float*)d_in[2];
    const float* w_hn = (const float*)d_in[3];
    const float* beta = (const float*)d_in[4];
    float* out = (float*)d_out;

    uint8_t *g8, *wqk8, *whn8, *QK8;
    cudaGetSymbolAddress((void**)&g8,   g_g8);
    cudaGetSymbolAddress((void**)&wqk8, g_wqk8);
    cudaGetSymbolAddress((void**)&whn8, g_whn8);
    cudaGetSymbolAddress((void**)&QK8,  g_QK8);

    cudaFuncSetAttribute(qk_gemm_kernel,
                         cudaFuncAttributeMaxDynamicSharedMemorySize, SMEM_DYN);
    cudaFuncSetAttribute(hn_attn_kernel,
                         cudaFuncAttributeMaxDynamicSharedMemorySize, SMEM_DYN);

    cvt_all_kernel<<<CVT_BLOCKS, 256>>>(g, wq, wk, w_hn);

    // [Q|K] = g @ [wq|wk]^T -> e4m3 (Q log2-domain pre-scale)
    qk_gemm_kernel<<<dim3(QKN / 128, ROWS / 128), 256, SMEM_DYN>>>(g8, wqk8, QK8, beta);

    // Fused: Hopfield GEMM (+LSE partials) and fp8 attention, one launch
    hn_attn_kernel<<<FUSED_BLOCKS, 256, SMEM_DYN>>>(g8, whn8, beta);

    hn_combine_kernel<<<ROWS / 256, 256>>>();

    finalize_kernel<<<1, 1>>>(beta, out);
}

// round 12
// speedup vs baseline: 1.0251x; 1.0251x over previous
#include <cuda_runtime.h>
#include <cuda_bf16.h>
#include <cuda_fp8.h>
#include <math.h>
#include <stdint.h>

// Problem constants
#define Bb   8
#define SEQ  1024
#define Dd   768
#define Hh   12
#define Zz   64
#define Mm   3072
#define ROWS (Bb * SEQ)           // 8192
#define QKN  (2 * Dd)             // 1536 (Q cols then K cols)
#define NTIL (Mm / 128)           // 24 hopfield n-tiles
#define ATTN_BETA 0.125f
#define LOG2E 1.4426950408889634f
#define LN2   0.6931471805599453f
#define WSCALE 16.0f              // weight pre-scale (power of 2, exact)
#define WUNSCALE 0.0625f
#define QSCALE (WUNSCALE * ATTN_BETA * LOG2E)   // Q cols -> log2-domain scores

// scratch (device globals: allocation-guard safe)
__device__ uint8_t       g_g8  [(size_t)ROWS * Dd];
__device__ uint8_t       g_wqk8[QKN * Dd];
__device__ uint8_t       g_whn8[Mm * Dd];
__device__ __nv_bfloat16 g_QKb [(size_t)ROWS * QKN];   // 25 MB bf16 Q|K
__device__ float         g_hn_part[(size_t)ROWS * NTIL];
__device__ int           g_qkflag[64 * 12];            // QK tile readiness
__device__ double        g_attn_sum;
__device__ double        g_hn_sum;

// ---------------------------------------------------------------------------
// Merged conversion kernel: zeros sums+flags, converts g/wq/wk/w_hn to e4m3.
// ---------------------------------------------------------------------------
#define NG_BLK  (ROWS * Dd / 2048)          // 3072
#define NW_BLK  (Hh * Zz * Dd / 2048)       // 288
#define NH_BLK  (Mm * Dd / 2048)            // 1152
#define CVT_BLOCKS (NG_BLK + 2 * NW_BLK + NH_BLK)

__global__ void cvt_all_kernel(const float* __restrict__ g,
                               const float* __restrict__ wq,
                               const float* __restrict__ wk,
                               const float* __restrict__ whn) {
    if (blockIdx.x == 0) {
        if (threadIdx.x == 0) { g_attn_sum = 0.0; g_hn_sum = 0.0; }
        for (int i = threadIdx.x; i < 64 * 12; i += 256) g_qkflag[i] = 0;
    }
    int b = blockIdx.x;
    const float* src; uint8_t* dst; float scale;
    if (b < NG_BLK)                       { src = g;   dst = g_g8;              scale = 1.0f;  }
    else if ((b -= NG_BLK) < NW_BLK)      { src = wq;  dst = g_wqk8;            scale = WSCALE; }
    else if ((b -= NW_BLK) < NW_BLK)      { src = wk;  dst = g_wqk8 + Hh*Zz*Dd; scale = WSCALE; }
    else { b -= NW_BLK;                     src = whn; dst = g_whn8;            scale = WSCALE; }

    int i = (b * 256 + threadIdx.x) * 8;
    float4 a = *(const float4*)(src + i);
    float4 c = *(const float4*)(src + i + 4);
    __nv_fp8x2_storage_t p0 = __nv_cvt_float2_to_fp8x2(
        make_float2(a.x * scale, a.y * scale), __NV_SATFINITE, __NV_E4M3);
    __nv_fp8x2_storage_t p1 = __nv_cvt_float2_to_fp8x2(
        make_float2(a.z * scale, a.w * scale), __NV_SATFINITE, __NV_E4M3);
    __nv_fp8x2_storage_t p2 = __nv_cvt_float2_to_fp8x2(
        make_float2(c.x * scale, c.y * scale), __NV_SATFINITE, __NV_E4M3);
    __nv_fp8x2_storage_t p3 = __nv_cvt_float2_to_fp8x2(
        make_float2(c.z * scale, c.w * scale), __NV_SATFINITE, __NV_E4M3);
    uint2 o;
    o.x = (uint32_t)p0 | ((uint32_t)p1 << 16);
    o.y = (uint32_t)p2 | ((uint32_t)p3 << 16);
    *(uint2*)(dst + i) = o;
}

// ---------------------------------------------------------------------------
// PTX helpers
// ---------------------------------------------------------------------------
__device__ __forceinline__ uint32_t smem_u32(const void* p) {
    return (uint32_t)__cvta_generic_to_shared(p);
}
__device__ __forceinline__ void ldsm_x4(uint32_t& r0, uint32_t& r1,
                                        uint32_t& r2, uint32_t& r3, uint32_t addr) {
    asm volatile("ldmatrix.sync.aligned.m8n8.x4.shared.b16 {%0,%1,%2,%3}, [%4];"
                 : "=r"(r0), "=r"(r1), "=r"(r2), "=r"(r3) : "r"(addr));
}
__device__ __forceinline__ void mma_bf16(float* d, const uint32_t* a, const uint32_t* b) {
    asm volatile(
        "mma.sync.aligned.m16n8k16.row.col.f32.bf16.bf16.f32 "
        "{%0,%1,%2,%3}, {%4,%5,%6,%7}, {%8,%9}, {%0,%1,%2,%3};"
        : "+f"(d[0]), "+f"(d[1]), "+f"(d[2]), "+f"(d[3])
        : "r"(a[0]), "r"(a[1]), "r"(a[2]), "r"(a[3]), "r"(b[0]), "r"(b[1]));
}
__device__ __forceinline__ void mma_fp8(float* d, const uint32_t* a, const uint32_t* b) {
    asm volatile(
        "mma.sync.aligned.m16n8k32.row.col.f32.e4m3.e4m3.f32 "
        "{%0,%1,%2,%3}, {%4,%5,%6,%7}, {%8,%9}, {%0,%1,%2,%3};"
        : "+f"(d[0]), "+f"(d[1]), "+f"(d[2]), "+f"(d[3])
        : "r"(a[0]), "r"(a[1]), "r"(a[2]), "r"(a[3]), "r"(b[0]), "r"(b[1]));
}
__device__ __forceinline__ void cp16(uint32_t smem, const void* g) {
    asm volatile("cp.async.cg.shared.global [%0], [%1], 16;" :: "r"(smem), "l"(g));
}
__device__ __forceinline__ void cp_commit() {
    asm volatile("cp.async.commit_group;" ::: "memory");
}
template <int N>
__device__ __forceinline__ void cp_wait() {
    asm volatile("cp.async.wait_group %0;" :: "n"(N) : "memory");
}
__device__ __forceinline__ float fex2(float x) {
    float r;
    asm("ex2.approx.ftz.f32 %0, %1;" : "=f"(r) : "f"(x));
    return r;
}
__device__ __forceinline__ float exp2_sum16(const float* v) {
    float e[16];
#pragma unroll
    for (int u = 0; u < 16; ++u) e[u] = fex2(v[u]);
#pragma unroll
    for (int st = 8; st > 0; st >>= 1)
#pragma unroll
        for (int u = 0; u < st; ++u) e[u] += e[u + st];
    return e[0];
}
// consumer-side readiness wait (tid0 polls, block barrier broadcasts)
__device__ __forceinline__ void wait_flag(int idx) {
    if (threadIdx.x == 0) {
        while (atomicAdd(&g_qkflag[idx], 0) == 0) { }
    }
    __syncthreads();
}

#define GSTR  80                 // bytes per smem row (64 + 16 pad)
#define STG_B (128 * GSTR)       // 10240 bytes per operand per stage
#define NCH8  (Dd / 64)          // 12 chunks
#define SMEM_DYN (3 * 2 * STG_B) // 61440 B
#define ALDS 72                  // attn smem row stride (bf16 elems)

// ---------------------------------------------------------------------------
// FP8 GEMM body. FUSE=false: store bf16 C (Q tile absorbs beta*log2e) and
// signal g_qkflag[by*12+bx]. FUSE=true: fused Hopfield exp2-sum partials.
// ---------------------------------------------------------------------------
template <bool FUSE>
__device__ __forceinline__
void gemm_body(char* dynsm, float (*red)[128], int bx, int by,
               const uint8_t* __restrict__ A, const uint8_t* __restrict__ B,
               __nv_bfloat16* __restrict__ C, int N,
               const float* __restrict__ beta_ptr) {
    const int tid  = threadIdx.x;
    const int warp = tid >> 5, lane = tid & 31;
    const int wm = warp >> 1, wn = warp & 1;
    const int m0 = by * 128, n0 = bx * 128;

    const int lrow0 = tid >> 2, lc4 = tid & 3;
    const uint8_t* Ag0 = A + (size_t)(m0 + lrow0) * Dd + lc4 * 16;
    const uint8_t* Ag1 = A + (size_t)(m0 + lrow0 + 64) * Dd + lc4 * 16;
    const uint8_t* Bg0 = B + (size_t)(n0 + lrow0) * Dd + lc4 * 16;
    const uint8_t* Bg1 = B + (size_t)(n0 + lrow0 + 64) * Dd + lc4 * 16;
    const uint32_t so0 = (uint32_t)(lrow0 * GSTR + lc4 * 16);
    const uint32_t so1 = so0 + (uint32_t)(64 * GSTR);
    const uint32_t smbase = smem_u32(dynsm);

    float acc[2][8][4];
#pragma unroll
    for (int i = 0; i < 2; ++i)
#pragma unroll
        for (int j = 0; j < 8; ++j)
#pragma unroll
            for (int k = 0; k < 4; ++k) acc[i][j][k] = 0.0f;

    const int arow   = wm * 32 + (lane & 15);
    const int acolB  = (lane >> 4) * 16;
    const int brow   = wn * 64 + (lane >> 4) * 8 + (lane & 7);
    const int bcolB  = ((lane >> 3) & 1) * 16;

    auto issue_chunk = [&](int j, int s) {
        const uint32_t ab = smbase + (uint32_t)(s * 2 * STG_B);
        const uint32_t bb = ab + STG_B;
        const int k0 = j * 64;
        cp16(ab + so0, Ag0 + k0);
        cp16(ab + so1, Ag1 + k0);
        cp16(bb + so0, Bg0 + k0);
        cp16(bb + so1, Bg1 + k0);
    };

    issue_chunk(0, 0); cp_commit();
    issue_chunk(1, 1); cp_commit();

    int stage = 0;
    for (int j = 0; j < NCH8; ++j) {
        cp_wait<1>();
        __syncthreads();
        if (j + 2 < NCH8) issue_chunk(j + 2, (stage + 2) % 3);
        cp_commit();

        const uint32_t ab = smbase + (uint32_t)(stage * 2 * STG_B);
        const uint32_t bb = ab + STG_B;
#pragma unroll
        for (int kk = 0; kk < 64; kk += 32) {
            uint32_t af[2][4];
#pragma unroll
            for (int mt = 0; mt < 2; ++mt)
                ldsm_x4(af[mt][0], af[mt][1], af[mt][2], af[mt][3],
                        ab + (uint32_t)((arow + mt * 16) * GSTR + acolB + kk));
            uint32_t bfr[4][4];
#pragma unroll
            for (int jj = 0; jj < 4; ++jj)
                ldsm_x4(bfr[jj][0], bfr[jj][1], bfr[jj][2], bfr[jj][3],
                        bb + (uint32_t)((brow + jj * 16) * GSTR + bcolB + kk));
#pragma unroll
            for (int mt = 0; mt < 2; ++mt)
#pragma unroll
                for (int jj = 0; jj < 4; ++jj) {
                    mma_fp8(acc[mt][2 * jj],     af[mt], &bfr[jj][0]);
                    mma_fp8(acc[mt][2 * jj + 1], af[mt], &bfr[jj][2]);
                }
        }
        stage = (stage + 1) % 3;
    }

    if (!FUSE) {
        const float sc = (n0 < Dd) ? QSCALE : WUNSCALE;
#pragma unroll
        for (int mt = 0; mt < 2; ++mt) {
            const int r = m0 + wm * 32 + mt * 16 + (lane >> 2);
#pragma unroll
            for (int nt = 0; nt < 8; ++nt) {
                const int c = n0 + wn * 64 + nt * 8 + (lane & 3) * 2;
                *(__nv_bfloat162*)(C + (size_t)r * N + c) =
                    __float22bfloat162_rn(make_float2(acc[mt][nt][0] * sc,
                                                      acc[mt][nt][1] * sc));
                *(__nv_bfloat162*)(C + (size_t)(r + 8) * N + c) =
                    __float22bfloat162_rn(make_float2(acc[mt][nt][2] * sc,
                                                      acc[mt][nt][3] * sc));
            }
        }
        // publish tile readiness (all stores -> fence -> barrier -> flag)
        __threadfence();
        __syncthreads();
        if (tid == 0) atomicExch(&g_qkflag[by * 12 + bx], 1);
    } else {
        const float SC = beta_ptr[0] * LOG2E * WUNSCALE;
        float Sl[2][2];
#pragma unroll
        for (int mt = 0; mt < 2; ++mt) {
#pragma unroll
            for (int half = 0; half < 2; ++half) {
                float v[16];
#pragma unroll
                for (int nt = 0; nt < 8; ++nt) {
                    v[2 * nt]     = acc[mt][nt][2 * half]     * SC;
                    v[2 * nt + 1] = acc[mt][nt][2 * half + 1] * SC;
                }
                float S = exp2_sum16(v);
                S += __shfl_xor_sync(0xffffffffu, S, 1);
                S += __shfl_xor_sync(0xffffffffu, S, 2);
                Sl[mt][half] = S;
            }
        }
        if ((lane & 3) == 0) {
#pragma unroll
            for (int mt = 0; mt < 2; ++mt)
#pragma unroll
                for (int half = 0; half < 2; ++half)
                    red[wn][wm * 32 + mt * 16 + half * 8 + (lane >> 2)] = Sl[mt][half];
        }
        __syncthreads();
        if (tid < 128) {
            g_hn_part[(size_t)(m0 + tid) * NTIL + bx] = red[0][tid] + red[1][tid];
        }
    }
}

// ---------------------------------------------------------------------------
// Attention body (bf16 mma, Q pre-scaled to log2 domain, exp2-sum, no max).
// q-tile 128, K streamed in 64-row tiles. Guards reads with g_qkflag.
// ---------------------------------------------------------------------------
__device__ __forceinline__
void attn_body(char* dynsm, float* red, int att_idx) {
    const int qt = att_idx & 7;
    const int h  = (att_idx >> 3) % Hh;
    const int b  = att_idx / (8 * Hh);
    const int q0 = qt * 128;

    __nv_bfloat16* Qs  = (__nv_bfloat16*)dynsm;                 // 128*72*2 = 18432
    __nv_bfloat16* Ks0 = (__nv_bfloat16*)(dynsm + 18432);       // 64*72*2 = 9216
    __nv_bfloat16* Ks1 = (__nv_bfloat16*)(dynsm + 18432 + 9216);

    const int tid  = threadIdx.x;
    const int wm   = tid >> 5, lane = tid & 31;

    const __nv_bfloat16* Kbase = g_QKb + (size_t)(b * SEQ) * QKN + Dd + h * Zz;
    __nv_bfloat16* KsArr[2] = { Ks0, Ks1 };

    const int kcol = 6 + (h >> 1);          // QK flag column for this head's K
    const int qrowblk = b * 8 + qt;

    auto issue_k = [&](int kt, int s) {
#pragma unroll
        for (int t = 0; t < 2; ++t) {
            int idx = tid + t * 256;
            int row = idx >> 3, ch = (idx & 7) * 8;
            cp16(smem_u32(KsArr[s] + row * ALDS + ch),
                 Kbase + (size_t)(kt * 64 + row) * QKN + ch);
        }
    };

    // wait for Q tile + first K tile to be produced
    wait_flag(qrowblk * 12 + (h >> 1));
    wait_flag((b * 8 + 0) * 12 + kcol);

    {
#pragma unroll
        for (int i = 0; i < 4; ++i) {
            int idx = tid + i * 256;
            int row = idx >> 3, ch = (idx & 7) * 8;
            cp16(smem_u32(Qs + row * ALDS + ch),
                 g_QKb + (size_t)(b * SEQ + q0 + row) * QKN + h * Zz + ch);
        }
        cp_commit();
    }
    issue_k(0, 0); cp_commit();

    cp_wait<1>();
    __syncthreads();

    const uint32_t qs_b = smem_u32(Qs);
    uint32_t qf[4][4];
    {
        const int arow = wm * 16 + (lane & 15);
        const int acol = (lane >> 4) * 8;
#pragma unroll
        for (int zs = 0; zs < 4; ++zs)
            ldsm_x4(qf[zs][0], qf[zs][1], qf[zs][2], qf[zs][3],
                    qs_b + (uint32_t)((arow * ALDS + acol + zs * 16) * 2));
    }

    const int brow = (lane >> 4) * 8 + (lane & 7);
    const int bcol = ((lane >> 3) & 1) * 8;

    float Ssum[2] = {0.0f, 0.0f};

    for (int kt = 0; kt < 16; ++kt) {
        cp_wait<0>();
        __syncthreads();
        if (kt + 1 < 16) {
            wait_flag((b * 8 + ((kt + 1) >> 1)) * 12 + kcol);
            issue_k(kt + 1, (kt + 1) & 1);
        }
        cp_commit();

        const uint32_t ks_b = smem_u32(KsArr[kt & 1]);

        float acc[8][4];
#pragma unroll
        for (int j = 0; j < 8; ++j)
#pragma unroll
            for (int k = 0; k < 4; ++k) acc[j][k] = 0.0f;

#pragma unroll
        for (int zs = 0; zs < 4; ++zs) {
            uint32_t bfr[4][4];
#pragma unroll
            for (int j = 0; j < 4; ++j)
                ldsm_x4(bfr[j][0], bfr[j][1], bfr[j][2], bfr[j][3],
                        ks_b + (uint32_t)(((brow + j * 16) * ALDS + bcol + zs * 16) * 2));
#pragma unroll
            for (int j = 0; j < 4; ++j) {
                mma_bf16(acc[2 * j],     qf[zs], &bfr[j][0]);
                mma_bf16(acc[2 * j + 1], qf[zs], &bfr[j][2]);
            }
        }

        // accs are log2-domain scores: f32 exp2 + tree sum, no max needed
#pragma unroll
        for (int half = 0; half < 2; ++half) {
            float v[16];
#pragma unroll
            for (int j = 0; j < 8; ++j) {
                v[2 * j]     = acc[j][2 * half];
                v[2 * j + 1] = acc[j][2 * half + 1];
            }
            Ssum[half] += exp2_sum16(v);
        }
    }

#pragma unroll
    for (int half = 0; half < 2; ++half) {
        float s = Ssum[half];
        s += __shfl_xor_sync(0xffffffffu, s, 1);
        s += __shfl_xor_sync(0xffffffffu, s, 2);
        if ((lane & 3) == 0)
            red[wm * 16 + (lane >> 2) + half * 8] = s;
    }
    __syncthreads();

    if (tid < 128) {
        float lse = logf(red[tid]);
#pragma unroll
        for (int o = 16; o > 0; o >>= 1)
            lse += __shfl_xor_sync(0xffffffffu, lse, o);
        if ((tid & 31) == 0) atomicAdd(&g_attn_sum, (double)lse);
    }
}

// ---------------------------------------------------------------------------
// THE fused kernel: blocks [0,768) = QK GEMM (producers), then 2:1
// interleaved Hopfield GEMM (1536) and attention (768, consumers, last).
// ---------------------------------------------------------------------------
#define QK_BLOCKS  (12 * 64)               // 768
#define HN_BLOCKS  (NTIL * (ROWS / 128))   // 1536
#define ATT_BLOCKS (8 * Hh * Bb)           // 768
#define ALL_BLOCKS (QK_BLOCKS + HN_BLOCKS + ATT_BLOCKS)   // 3072

__global__ __launch_bounds__(256, 2)
void et_fused_kernel(const uint8_t* __restrict__ g8,
                     const uint8_t* __restrict__ wqk8,
                     const uint8_t* __restrict__ whn8,
                     __nv_bfloat16* __restrict__ QKb,
                     const float* __restrict__ beta_ptr) {
    extern __shared__ char dynsm[];
    __shared__ float red[2][128];
    const int bid = blockIdx.x;
    if (bid < QK_BLOCKS) {
        gemm_body<false>(dynsm, red, bid % 12, bid / 12, g8, wqk8, QKb, QKN, beta_ptr);
    } else {
        const int fb = bid - QK_BLOCKS;
        const int grp = fb / 3, r = fb - grp * 3;
        if (r < 2) {
            const int hn_idx = grp * 2 + r;
            gemm_body<true>(dynsm, red, hn_idx % NTIL, hn_idx / NTIL,
                            g8, whn8, nullptr, Mm, beta_ptr);
        } else {
            attn_body(dynsm, &red[0][0], grp);
        }
    }
}

// ---------------------------------------------------------------------------
// Combine Hopfield partials (float4 loads) + finalize
// ---------------------------------------------------------------------------
__global__ void hn_combine_kernel() {
    const int row = blockIdx.x * 256 + threadIdx.x;
    const float4* part = (const float4*)(g_hn_part + (size_t)row * NTIL);
    float4 p0 = part[0], p1 = part[1], p2 = part[2];
    float4 p3 = part[3], p4 = part[4], p5 = part[5];
    float S = ((p0.x + p0.y) + (p0.z + p0.w)) + ((p1.x + p1.y) + (p1.z + p1.w))
            + ((p2.x + p2.y) + (p2.z + p2.w)) + ((p3.x + p3.y) + (p3.z + p3.w))
            + ((p4.x + p4.y) + (p4.z + p4.w)) + ((p5.x + p5.y) + (p5.z + p5.w));
    float lse = logf(S);

    __shared__ float smr[256];
    smr[threadIdx.x] = lse;
    __syncthreads();
    for (int st = 128; st > 0; st >>= 1) {
        if (threadIdx.x < st) smr[threadIdx.x] += smr[threadIdx.x + st];
        __syncthreads();
    }
    if (threadIdx.x == 0) atomicAdd(&g_hn_sum, (double)smr[0]);
}

__global__ void finalize_kernel(const float* __restrict__ beta_ptr, float* out) {
    double beta = (double)beta_ptr[0];
    out[0] = (float)(-8.0 * g_attn_sum - (1.0 / beta) * g_hn_sum);
}

// ---------------------------------------------------------------------------
extern "C" void kernel_launch(void* const* d_in, const int* in_sizes, int n_in,
                              void* d_out, int out_size) {
    (void)in_sizes; (void)n_in; (void)out_size;
    const float* g    = (const float*)d_in[0];
    const float* wq   = (const float*)d_in[1];
    const float* wk   = (const float*)d_in[2];
    const float* w_hn = (const float*)d_in[3];
    const float* beta = (const float*)d_in[4];
    float* out = (float*)d_out;

    uint8_t *g8, *wqk8, *whn8;
    __nv_bfloat16* QKb;
    cudaGetSymbolAddress((void**)&g8,   g_g8);
    cudaGetSymbolAddress((void**)&wqk8, g_wqk8);
    cudaGetSymbolAddress((void**)&whn8, g_whn8);
    cudaGetSymbolAddress((void**)&QKb,  g_QKb);

    cudaFuncSetAttribute(et_fused_kernel,
                         cudaFuncAttributeMaxDynamicSharedMemorySize, SMEM_DYN);

    cvt_all_kernel<<<CVT_BLOCKS, 256>>>(g, wq, wk, w_hn);

    // One fused launch: QK GEMM producers -> Hopfield GEMM + attention
    et_fused_kernel<<<ALL_BLOCKS, 256, SMEM_DYN>>>(g8, wqk8, whn8, QKb, beta);

    hn_combine_kernel<<<ROWS / 256, 256>>>();

    finalize_kernel<<<1, 1>>>(beta, out);
}

// round 13
// speedup vs baseline: 1.0809x; 1.0544x over previous
#include <cuda_runtime.h>
#include <cuda_bf16.h>
#include <cuda_fp8.h>
#include <math.h>
#include <stdint.h>

// Problem constants
#define Bb   8
#define SEQ  1024
#define Dd   768
#define Hh   12
#define Zz   64
#define Mm   3072
#define ROWS (Bb * SEQ)           // 8192
#define QKN  (2 * Dd)             // 1536 (Q cols then K cols)
#define NTIL (Mm / 128)           // 24 hopfield n-tiles
#define ATTN_BETA 0.125f
#define LOG2E 1.4426950408889634f
#define LN2   0.6931471805599453f
#define WSCALE 16.0f              // weight pre-scale (power of 2, exact)
#define WUNSCALE 0.0625f
#define QSCALE (WUNSCALE * ATTN_BETA * LOG2E)   // Q cols -> log2-domain scores

// scratch (device globals: allocation-guard safe)
__device__ uint8_t       g_g8  [(size_t)ROWS * Dd];
__device__ uint8_t       g_wqk8[QKN * Dd];
__device__ uint8_t       g_whn8[Mm * Dd];
__device__ __nv_bfloat16 g_QKb [(size_t)ROWS * QKN];   // 25 MB bf16 Q|K
__device__ float         g_hn_part[(size_t)ROWS * NTIL];
__device__ int           g_cmb_cnt;
__device__ double        g_attn_sum;
__device__ double        g_hn_sum;

// ---------------------------------------------------------------------------
// Merged conversion kernel: zeros sums+counter, converts g/wq/wk/w_hn to e4m3.
// ---------------------------------------------------------------------------
#define NG_BLK  (ROWS * Dd / 2048)          // 3072
#define NW_BLK  (Hh * Zz * Dd / 2048)       // 288
#define NH_BLK  (Mm * Dd / 2048)            // 1152
#define CVT_BLOCKS (NG_BLK + 2 * NW_BLK + NH_BLK)

__global__ void cvt_all_kernel(const float* __restrict__ g,
                               const float* __restrict__ wq,
                               const float* __restrict__ wk,
                               const float* __restrict__ whn) {
    if (blockIdx.x == 0 && threadIdx.x == 0) {
        g_attn_sum = 0.0; g_hn_sum = 0.0; g_cmb_cnt = 0;
    }
    int b = blockIdx.x;
    const float* src; uint8_t* dst; float scale;
    if (b < NG_BLK)                       { src = g;   dst = g_g8;              scale = 1.0f;  }
    else if ((b -= NG_BLK) < NW_BLK)      { src = wq;  dst = g_wqk8;            scale = WSCALE; }
    else if ((b -= NW_BLK) < NW_BLK)      { src = wk;  dst = g_wqk8 + Hh*Zz*Dd; scale = WSCALE; }
    else { b -= NW_BLK;                     src = whn; dst = g_whn8;            scale = WSCALE; }

    int i = (b * 256 + threadIdx.x) * 8;
    float4 a = *(const float4*)(src + i);
    float4 c = *(const float4*)(src + i + 4);
    __nv_fp8x2_storage_t p0 = __nv_cvt_float2_to_fp8x2(
        make_float2(a.x * scale, a.y * scale), __NV_SATFINITE, __NV_E4M3);
    __nv_fp8x2_storage_t p1 = __nv_cvt_float2_to_fp8x2(
        make_float2(a.z * scale, a.w * scale), __NV_SATFINITE, __NV_E4M3);
    __nv_fp8x2_storage_t p2 = __nv_cvt_float2_to_fp8x2(
        make_float2(c.x * scale, c.y * scale), __NV_SATFINITE, __NV_E4M3);
    __nv_fp8x2_storage_t p3 = __nv_cvt_float2_to_fp8x2(
        make_float2(c.z * scale, c.w * scale), __NV_SATFINITE, __NV_E4M3);
    uint2 o;
    o.x = (uint32_t)p0 | ((uint32_t)p1 << 16);
    o.y = (uint32_t)p2 | ((uint32_t)p3 << 16);
    *(uint2*)(dst + i) = o;
}

// ---------------------------------------------------------------------------
// PTX helpers
// ---------------------------------------------------------------------------
__device__ __forceinline__ uint32_t smem_u32(const void* p) {
    return (uint32_t)__cvta_generic_to_shared(p);
}
__device__ __forceinline__ void ldsm_x4(uint32_t& r0, uint32_t& r1,
                                        uint32_t& r2, uint32_t& r3, uint32_t addr) {
    asm volatile("ldmatrix.sync.aligned.m8n8.x4.shared.b16 {%0,%1,%2,%3}, [%4];"
                 : "=r"(r0), "=r"(r1), "=r"(r2), "=r"(r3) : "r"(addr));
}
__device__ __forceinline__ void mma_bf16(float* d, const uint32_t* a, const uint32_t* b) {
    asm volatile(
        "mma.sync.aligned.m16n8k16.row.col.f32.bf16.bf16.f32 "
        "{%0,%1,%2,%3}, {%4,%5,%6,%7}, {%8,%9}, {%0,%1,%2,%3};"
        : "+f"(d[0]), "+f"(d[1]), "+f"(d[2]), "+f"(d[3])
        : "r"(a[0]), "r"(a[1]), "r"(a[2]), "r"(a[3]), "r"(b[0]), "r"(b[1]));
}
__device__ __forceinline__ void mma_fp8(float* d, const uint32_t* a, const uint32_t* b) {
    asm volatile(
        "mma.sync.aligned.m16n8k32.row.col.f32.e4m3.e4m3.f32 "
        "{%0,%1,%2,%3}, {%4,%5,%6,%7}, {%8,%9}, {%0,%1,%2,%3};"
        : "+f"(d[0]), "+f"(d[1]), "+f"(d[2]), "+f"(d[3])
        : "r"(a[0]), "r"(a[1]), "r"(a[2]), "r"(a[3]), "r"(b[0]), "r"(b[1]));
}
__device__ __forceinline__ void cp16(uint32_t smem, const void* g) {
    asm volatile("cp.async.cg.shared.global [%0], [%1], 16;" :: "r"(smem), "l"(g));
}
__device__ __forceinline__ void cp_commit() {
    asm volatile("cp.async.commit_group;" ::: "memory");
}
template <int N>
__device__ __forceinline__ void cp_wait() {
    asm volatile("cp.async.wait_group %0;" :: "n"(N) : "memory");
}
__device__ __forceinline__ float fex2(float x) {
    float r;
    asm("ex2.approx.ftz.f32 %0, %1;" : "=f"(r) : "f"(x));
    return r;
}
__device__ __forceinline__ float exp2_sum16(const float* v) {
    float e[16];
#pragma unroll
    for (int u = 0; u < 16; ++u) e[u] = fex2(v[u]);
#pragma unroll
    for (int st = 8; st > 0; st >>= 1)
#pragma unroll
        for (int u = 0; u < st; ++u) e[u] += e[u + st];
    return e[0];
}

#define GSTR  80                 // bytes per smem row (64 + 16 pad)
#define STG_B (128 * GSTR)       // 10240 bytes per operand per stage
#define NCH8  (Dd / 64)          // 12 chunks
#define SMEM_DYN (3 * 2 * STG_B) // 61440 B
#define ALDS 72                  // attn smem row stride (bf16 elems)

// ---------------------------------------------------------------------------
// FP8 GEMM body. FUSE=false: store bf16 C (Q tile absorbs beta*log2e).
// FUSE=true: fused Hopfield exp2-sum partials.
// ---------------------------------------------------------------------------
template <bool FUSE>
__device__ __forceinline__
void gemm_body(char* dynsm, float (*red)[128], int bx, int by,
               const uint8_t* __restrict__ A, const uint8_t* __restrict__ B,
               __nv_bfloat16* __restrict__ C, int N,
               const float* __restrict__ beta_ptr) {
    const int tid  = threadIdx.x;
    const int warp = tid >> 5, lane = tid & 31;
    const int wm = warp >> 1, wn = warp & 1;
    const int m0 = by * 128, n0 = bx * 128;

    const int lrow0 = tid >> 2, lc4 = tid & 3;
    const uint8_t* Ag0 = A + (size_t)(m0 + lrow0) * Dd + lc4 * 16;
    const uint8_t* Ag1 = A + (size_t)(m0 + lrow0 + 64) * Dd + lc4 * 16;
    const uint8_t* Bg0 = B + (size_t)(n0 + lrow0) * Dd + lc4 * 16;
    const uint8_t* Bg1 = B + (size_t)(n0 + lrow0 + 64) * Dd + lc4 * 16;
    const uint32_t so0 = (uint32_t)(lrow0 * GSTR + lc4 * 16);
    const uint32_t so1 = so0 + (uint32_t)(64 * GSTR);
    const uint32_t smbase = smem_u32(dynsm);

    float acc[2][8][4];
#pragma unroll
    for (int i = 0; i < 2; ++i)
#pragma unroll
        for (int j = 0; j < 8; ++j)
#pragma unroll
            for (int k = 0; k < 4; ++k) acc[i][j][k] = 0.0f;

    const int arow   = wm * 32 + (lane & 15);
    const int acolB  = (lane >> 4) * 16;
    const int brow   = wn * 64 + (lane >> 4) * 8 + (lane & 7);
    const int bcolB  = ((lane >> 3) & 1) * 16;

    auto issue_chunk = [&](int j, int s) {
        const uint32_t ab = smbase + (uint32_t)(s * 2 * STG_B);
        const uint32_t bb = ab + STG_B;
        const int k0 = j * 64;
        cp16(ab + so0, Ag0 + k0);
        cp16(ab + so1, Ag1 + k0);
        cp16(bb + so0, Bg0 + k0);
        cp16(bb + so1, Bg1 + k0);
    };

    issue_chunk(0, 0); cp_commit();
    issue_chunk(1, 1); cp_commit();

    int stage = 0;
    for (int j = 0; j < NCH8; ++j) {
        cp_wait<1>();
        __syncthreads();
        if (j + 2 < NCH8) issue_chunk(j + 2, (stage + 2) % 3);
        cp_commit();

        const uint32_t ab = smbase + (uint32_t)(stage * 2 * STG_B);
        const uint32_t bb = ab + STG_B;
#pragma unroll
        for (int kk = 0; kk < 64; kk += 32) {
            uint32_t af[2][4];
#pragma unroll
            for (int mt = 0; mt < 2; ++mt)
                ldsm_x4(af[mt][0], af[mt][1], af[mt][2], af[mt][3],
                        ab + (uint32_t)((arow + mt * 16) * GSTR + acolB + kk));
            uint32_t bfr[4][4];
#pragma unroll
            for (int jj = 0; jj < 4; ++jj)
                ldsm_x4(bfr[jj][0], bfr[jj][1], bfr[jj][2], bfr[jj][3],
                        bb + (uint32_t)((brow + jj * 16) * GSTR + bcolB + kk));
#pragma unroll
            for (int mt = 0; mt < 2; ++mt)
#pragma unroll
                for (int jj = 0; jj < 4; ++jj) {
                    mma_fp8(acc[mt][2 * jj],     af[mt], &bfr[jj][0]);
                    mma_fp8(acc[mt][2 * jj + 1], af[mt], &bfr[jj][2]);
                }
        }
        stage = (stage + 1) % 3;
    }

    if (!FUSE) {
        const float sc = (n0 < Dd) ? QSCALE : WUNSCALE;
#pragma unroll
        for (int mt = 0; mt < 2; ++mt) {
            const int r = m0 + wm * 32 + mt * 16 + (lane >> 2);
#pragma unroll
            for (int nt = 0; nt < 8; ++nt) {
                const int c = n0 + wn * 64 + nt * 8 + (lane & 3) * 2;
                *(__nv_bfloat162*)(C + (size_t)r * N + c) =
                    __float22bfloat162_rn(make_float2(acc[mt][nt][0] * sc,
                                                      acc[mt][nt][1] * sc));
                *(__nv_bfloat162*)(C + (size_t)(r + 8) * N + c) =
                    __float22bfloat162_rn(make_float2(acc[mt][nt][2] * sc,
                                                      acc[mt][nt][3] * sc));
            }
        }
    } else {
        const float SC = beta_ptr[0] * LOG2E * WUNSCALE;
        float Sl[2][2];
#pragma unroll
        for (int mt = 0; mt < 2; ++mt) {
#pragma unroll
            for (int half = 0; half < 2; ++half) {
                float v[16];
#pragma unroll
                for (int nt = 0; nt < 8; ++nt) {
                    v[2 * nt]     = acc[mt][nt][2 * half]     * SC;
                    v[2 * nt + 1] = acc[mt][nt][2 * half + 1] * SC;
                }
                float S = exp2_sum16(v);
                S += __shfl_xor_sync(0xffffffffu, S, 1);
                S += __shfl_xor_sync(0xffffffffu, S, 2);
                Sl[mt][half] = S;
            }
        }
        if ((lane & 3) == 0) {
#pragma unroll
            for (int mt = 0; mt < 2; ++mt)
#pragma unroll
                for (int half = 0; half < 2; ++half)
                    red[wn][wm * 32 + mt * 16 + half * 8 + (lane >> 2)] = Sl[mt][half];
        }
        __syncthreads();
        if (tid < 128) {
            g_hn_part[(size_t)(m0 + tid) * NTIL + bx] = red[0][tid] + red[1][tid];
        }
    }
}

// ---------------------------------------------------------------------------
// Attention body: q-tile 256, warp = 32 q-rows. bf16 mma (Q log2-domain),
// exp2-sum, no max. K streamed in 64-row tiles, cp.async double buffer.
// A-fragments reloaded per zs (GEMM-style) -> no persistent qf registers.
// ---------------------------------------------------------------------------
__device__ __forceinline__
void attn_body(char* dynsm, float* red, int att_idx) {
    const int qt = att_idx & 3;
    const int h  = (att_idx >> 2) % Hh;
    const int b  = att_idx / (4 * Hh);
    const int q0 = qt * 256;

    __nv_bfloat16* Qs  = (__nv_bfloat16*)dynsm;                 // 256*72*2 = 36864
    __nv_bfloat16* Ks0 = (__nv_bfloat16*)(dynsm + 36864);       // 64*72*2 = 9216
    __nv_bfloat16* Ks1 = (__nv_bfloat16*)(dynsm + 46080);

    const int tid = threadIdx.x;
    const int wm  = tid >> 5, lane = tid & 31;

    const __nv_bfloat16* Kbase = g_QKb + (size_t)(b * SEQ) * QKN + Dd + h * Zz;
    __nv_bfloat16* KsArr[2] = { Ks0, Ks1 };

    auto issue_k = [&](int kt, int s) {
#pragma unroll
        for (int t = 0; t < 2; ++t) {
            int idx = tid + t * 256;
            int row = idx >> 3, ch = (idx & 7) * 8;
            cp16(smem_u32(KsArr[s] + row * ALDS + ch),
                 Kbase + (size_t)(kt * 64 + row) * QKN + ch);
        }
    };

    // Q tile 256x64
    {
#pragma unroll
        for (int i = 0; i < 8; ++i) {
            int idx = tid + i * 256;
            int row = idx >> 3, ch = (idx & 7) * 8;
            cp16(smem_u32(Qs + row * ALDS + ch),
                 g_QKb + (size_t)(b * SEQ + q0 + row) * QKN + h * Zz + ch);
        }
        cp_commit();
    }
    issue_k(0, 0); cp_commit();

    cp_wait<1>();          // Q landed
    __syncthreads();

    const uint32_t qs_b = smem_u32(Qs);
    const int arow = wm * 32 + (lane & 15);     // +mt*16
    const int acol = (lane >> 4) * 8;
    const int brow = (lane >> 4) * 8 + (lane & 7);
    const int bcol = ((lane >> 3) & 1) * 8;

    float Ssum[2][2] = {{0.0f, 0.0f}, {0.0f, 0.0f}};

    for (int kt = 0; kt < 16; ++kt) {
        cp_wait<0>();
        __syncthreads();
        if (kt + 1 < 16) issue_k(kt + 1, (kt + 1) & 1);
        cp_commit();

        const uint32_t ks_b = smem_u32(KsArr[kt & 1]);

        float acc[2][8][4];
#pragma unroll
        for (int mt = 0; mt < 2; ++mt)
#pragma unroll
            for (int j = 0; j < 8; ++j)
#pragma unroll
                for (int k = 0; k < 4; ++k) acc[mt][j][k] = 0.0f;

#pragma unroll
        for (int zs = 0; zs < 4; ++zs) {
            uint32_t af[2][4];
#pragma unroll
            for (int mt = 0; mt < 2; ++mt)
                ldsm_x4(af[mt][0], af[mt][1], af[mt][2], af[mt][3],
                        qs_b + (uint32_t)(((arow + mt * 16) * ALDS + acol + zs * 16) * 2));
            uint32_t bfr[4][4];
#pragma unroll
            for (int j = 0; j < 4; ++j)
                ldsm_x4(bfr[j][0], bfr[j][1], bfr[j][2], bfr[j][3],
                        ks_b + (uint32_t)(((brow + j * 16) * ALDS + bcol + zs * 16) * 2));
#pragma unroll
            for (int mt = 0; mt < 2; ++mt)
#pragma unroll
                for (int j = 0; j < 4; ++j) {
                    mma_bf16(acc[mt][2 * j],     af[mt], &bfr[j][0]);
                    mma_bf16(acc[mt][2 * j + 1], af[mt], &bfr[j][2]);
                }
        }

        // accs are log2-domain scores: f32 exp2 + tree sum
#pragma unroll
        for (int mt = 0; mt < 2; ++mt)
#pragma unroll
            for (int half = 0; half < 2; ++half) {
                float v[16];
#pragma unroll
                for (int j = 0; j < 8; ++j) {
                    v[2 * j]     = acc[mt][j][2 * half];
                    v[2 * j + 1] = acc[mt][j][2 * half + 1];
                }
                Ssum[mt][half] += exp2_sum16(v);
            }
    }

    // quad merge -> per-row S (256 rows)
#pragma unroll
    for (int mt = 0; mt < 2; ++mt)
#pragma unroll
        for (int half = 0; half < 2; ++half) {
            float s = Ssum[mt][half];
            s += __shfl_xor_sync(0xffffffffu, s, 1);
            s += __shfl_xor_sync(0xffffffffu, s, 2);
            if ((lane & 3) == 0)
                red[wm * 32 + mt * 16 + half * 8 + (lane >> 2)] = s;
        }
    __syncthreads();

    {
        float lse = logf(red[tid]);
#pragma unroll
        for (int o = 16; o > 0; o >>= 1)
            lse += __shfl_xor_sync(0xffffffffu, lse, o);
        if ((tid & 31) == 0) atomicAdd(&g_attn_sum, (double)lse);
    }
}

// ---------------------------------------------------------------------------
// Kernel 1: QK projection GEMM.  grid = (QKN/128, ROWS/128)
// ---------------------------------------------------------------------------
__global__ __launch_bounds__(256, 2)
void qk_gemm_kernel(const uint8_t* __restrict__ A, const uint8_t* __restrict__ B,
                    __nv_bfloat16* __restrict__ C, const float* __restrict__ beta_ptr) {
    extern __shared__ char dynsm[];
    gemm_body<false>(dynsm, nullptr, blockIdx.x, blockIdx.y, A, B, C, QKN, beta_ptr);
}

// ---------------------------------------------------------------------------
// Kernel 2: FUSED Hopfield GEMM + attention, interleaved 1:4 with the
// (longer) attention CTAs first in each group (LPT scheduling).
// ---------------------------------------------------------------------------
#define HN_BLOCKS  (NTIL * (ROWS / 128))   // 1536
#define ATT_BLOCKS (4 * Hh * Bb)           // 384
#define FUSED_BLOCKS (HN_BLOCKS + ATT_BLOCKS)   // 1920

__global__ __launch_bounds__(256, 2)
void hn_attn_kernel(const uint8_t* __restrict__ A, const uint8_t* __restrict__ B,
                    const float* __restrict__ beta_ptr) {
    extern __shared__ char dynsm[];
    __shared__ float red[2][128];
    const int bid = blockIdx.x;
    const int grp = bid / 5, r = bid - grp * 5;
    if (r == 0) {
        attn_body(dynsm, &red[0][0], grp);
    } else {
        const int hn_idx = grp * 4 + (r - 1);
        gemm_body<true>(dynsm, red, hn_idx % NTIL, hn_idx / NTIL,
                        A, B, nullptr, Mm, beta_ptr);
    }
}

// ---------------------------------------------------------------------------
// Combine Hopfield partials (float4 loads); last block finalizes output.
// ---------------------------------------------------------------------------
__global__ void hn_combine_kernel(const float* __restrict__ beta_ptr,
                                  float* __restrict__ out) {
    const int row = blockIdx.x * 256 + threadIdx.x;
    const float4* part = (const float4*)(g_hn_part + (size_t)row * NTIL);
    float4 p0 = part[0], p1 = part[1], p2 = part[2];
    float4 p3 = part[3], p4 = part[4], p5 = part[5];
    float S = ((p0.x + p0.y) + (p0.z + p0.w)) + ((p1.x + p1.y) + (p1.z + p1.w))
            + ((p2.x + p2.y) + (p2.z + p2.w)) + ((p3.x + p3.y) + (p3.z + p3.w))
            + ((p4.x + p4.y) + (p4.z + p4.w)) + ((p5.x + p5.y) + (p5.z + p5.w));
    float lse = logf(S);

    __shared__ float smr[256];
    smr[threadIdx.x] = lse;
    __syncthreads();
    for (int st = 128; st > 0; st >>= 1) {
        if (threadIdx.x < st) smr[threadIdx.x] += smr[threadIdx.x + st];
        __syncthreads();
    }
    if (threadIdx.x == 0) {
        atomicAdd(&g_hn_sum, (double)smr[0]);
        __threadfence();
        int done = atomicAdd(&g_cmb_cnt, 1);
        if (done == (ROWS / 256) - 1) {
            double beta = (double)beta_ptr[0];
            out[0] = (float)(-8.0 * g_attn_sum - (1.0 / beta) * g_hn_sum);
        }
    }
}

// ---------------------------------------------------------------------------
extern "C" void kernel_launch(void* const* d_in, const int* in_sizes, int n_in,
                              void* d_out, int out_size) {
    (void)in_sizes; (void)n_in; (void)out_size;
    const float* g    = (const float*)d_in[0];
    const float* wq   = (const float*)d_in[1];
    const float* wk   = (const float*)d_in[2];
    const float* w_hn = (const float*)d_in[3];
    const float* beta = (const float*)d_in[4];
    float* out = (float*)d_out;

    uint8_t *g8, *wqk8, *whn8;
    __nv_bfloat16* QKb;
    cudaGetSymbolAddress((void**)&g8,   g_g8);
    cudaGetSymbolAddress((void**)&wqk8, g_wqk8);
    cudaGetSymbolAddress((void**)&whn8, g_whn8);
    cudaGetSymbolAddress((void**)&QKb,  g_QKb);

    cudaFuncSetAttribute(qk_gemm_kernel,
                         cudaFuncAttributeMaxDynamicSharedMemorySize, SMEM_DYN);
    cudaFuncSetAttribute(hn_attn_kernel,
                         cudaFuncAttributeMaxDynamicSharedMemorySize, SMEM_DYN);

    cvt_all_kernel<<<CVT_BLOCKS, 256>>>(g, wq, wk, w_hn);

    // [Q|K] = g @ [wq|wk]^T -> bf16 (Q log2-domain pre-scale)
    qk_gemm_kernel<<<dim3(QKN / 128, ROWS / 128), 256, SMEM_DYN>>>(g8, wqk8, QKb, beta);

    // Fused: Hopfield GEMM (+LSE partials) and attention, 1:4 interleave
    hn_attn_kernel<<<FUSED_BLOCKS, 256, SMEM_DYN>>>(g8, whn8, beta);

    // Combine Hopfield partials; last block writes the final output
    hn_combine_kernel<<<ROWS / 256, 256>>>(beta, out);
}